// round 16
// baseline (speedup 1.0000x reference)
#include <cuda_runtime.h>
#include <cuda_fp16.h>
#include <cstring>

#define NN     8192
#define TC     128
#define NCH    (NN / TC)                 // 64
#define NTILES (NCH * (NCH + 1) / 2)     // 2080 upper-tri tiles
#define NU     (NTILES * 4)              // 8320 quarter-tile work units
#define BLKSM  12
#define GRID   (148 * BLKSM)             // 1776 persistent blocks
#define LOG2E  1.4426950408889634f
#define LN2    0.6931471805599453

// Device-global scratch (allocation-free). The finalizing block resets
// everything after each run so graph replays are deterministic.
static __device__ double             g_sum  = 0.0;
static __device__ double             g_mse  = 0.0;
static __device__ unsigned long long g_cnt  = 0ull;
static __device__ unsigned int       g_done = 0u;
static __device__ unsigned int       g_unit = GRID;   // next work unit to hand out

__device__ __forceinline__ float fast_ex2(float x) {
    float y; asm("ex2.approx.ftz.f32 %0, %1;" : "=f"(y) : "f"(x)); return y;
}
__device__ __forceinline__ float fast_lg2(float x) {
    float y; asm("lg2.approx.ftz.f32 %0, %1;" : "=f"(y) : "f"(x)); return y;
}
__device__ __forceinline__ unsigned h2u(__half2 h) {
    unsigned u; memcpy(&u, &h, 4); return u;
}
__device__ __forceinline__ __half2 u2h(unsigned u) {
    __half2 h; memcpy(&h, &u, 4); return h;
}

// tiles before row b (rows bi <= bj): b*NCH - b(b-1)/2
__device__ __forceinline__ int tri_off(int b) { return b * NCH - (b * (b - 1)) / 2; }

// Full-precision scalar pair body (diagonal units only, ~3% of work).
__device__ __forceinline__ void pair_body(float ti, float pis, float tj, float pjs,
                                          float& sum, float& cnt) {
    float dt  = ti  - tj;
    float dps = pis - pjs;
    unsigned xb = __float_as_uint(dps) ^
                  ((__float_as_uint(dt) & 0x80000000u) ^ 0x80000000u);
    float u   = fast_ex2(__uint_as_float(xb));
    float l2  = fast_lg2(1.0f + u);
    float adt = fabsf(dt);
    if (adt > 0.1f) { sum = fmaf(adt, l2, sum); cnt += 1.0f; }
}

// Packed 2-pair group; EX2 fed straight from dps2 (2-link chain), sign/max
// moved off the critical path: z=-sign(dt)*dps; 2*log2(1+2^z)=2max(z,0)+2log2(1+2^-|dps|)
__device__ __forceinline__ void group2(unsigned hti, unsigned hpis,
                                       unsigned ntu, unsigned npu,
                                       const __half2& C1, const __half2& C2,
                                       const __half2& C3, const __half2& C4,
                                       const __half2& C5, const __half2& THR,
                                       __half2& sumh, __half2& cnth) {
    unsigned dt2  = h2u(__hadd2(u2h(hti),  u2h(ntu)));
    unsigned dps2 = h2u(__hadd2(u2h(hpis), u2h(npu)));
    unsigned nz2  = dps2 | 0x80008000u;                    // -|dps|
    unsigned uu;
    asm("ex2.approx.f16x2 %0, %1;" : "=r"(uu) : "r"(nz2)); // u = 2^-|z|
    unsigned az2  = dps2 & 0x7FFF7FFFu;                    // |z|
    unsigned sd2  = dps2 ^ (dt2 & 0x80008000u);            // sign(dt)*dps
    __half2 mm2   = __hsub2(u2h(az2), u2h(sd2));           // 2*max(z,0)
    __half2 uh    = u2h(uu);
    __half2 qp    = __hfma2(uh, C5, C4);
    qp = __hfma2(qp, uh, C3);
    qp = __hfma2(qp, uh, C2);
    qp = __hfma2(qp, uh, C1);
    __half2 l2x2  = __hfma2(qp, uh, mm2);                  // 2*log2(1+2^z)
    __half2 adt2  = u2h(dt2 & 0x7FFF7FFFu);
    __half2 ones  = __hgt2(adt2, THR);                     // 1.0 / 0.0
    __half2 wad   = __hmul2(adt2, ones);
    cnth = __hadd2(cnth, ones);
    sumh = __hfma2(wad, l2x2, sumh);
}

__global__ __launch_bounds__(TC, BLKSM)
void rk_persist(const float* __restrict__ pred, const float* __restrict__ targ,
                float* __restrict__ out) {
    // Quarter-tile j-window (32 j's): 8 uint4, packed (nt,np) half pairs.
    __shared__ uint4   su4[8];
    __shared__ float2  s2f[32];          // f32 (t, p*log2e), diagonal units only
    __shared__ float   red[3][TC / 32];
    __shared__ unsigned s_next;

    const int t = threadIdx.x;

    // 2*log2(1+u) = u*(C1 + u*(C2 + u*(C3 + u*(C4 + u*C5)))), u in (0,1]
    const __half2 C1 = __floats2half2_rn(2.884924f, 2.884924f);
    const __half2 C2 = __floats2half2_rn(-1.430090f, -1.430090f);
    const __half2 C3 = __floats2half2_rn(0.870912f, 0.870912f);
    const __half2 C4 = __floats2half2_rn(-0.438334f, -0.438334f);
    const __half2 C5 = __floats2half2_rn(0.112588f, 0.112588f);
    const __half2 THR = __floats2half2_rn(0.1f, 0.1f);

    float fsum = 0.f;                    // off-diag, log2-domain, x2 scaled
    float sdiag = 0.f;                   // diag, log2-domain, unscaled
    float fcnt = 0.f, msq = 0.f;

    unsigned u = blockIdx.x;             // units 0..GRID-1 statically, rest stolen
    while (u < NU) {
        const int k = (int)(u >> 2);     // tile
        const int q = (int)(u & 3u);     // j-window within tile
        float disc = (float)((2 * NCH + 1) * (2 * NCH + 1) - 8 * k);
        int bi = (int)(((float)(2 * NCH + 1) - sqrtf(disc)) * 0.5f);
        bi = min(max(bi, 0), NCH - 1);
        while (bi + 1 <= NCH - 1 && tri_off(bi + 1) <= k) ++bi;
        while (tri_off(bi) > k) --bi;
        const int bj = bi + (k - tri_off(bi));
        const bool diag = (bi == bj);

        const int jbase = bj * TC + q * 32;
        if (t < 32) {
            const float tj  = targ[jbase + t];
            const float pjs = pred[jbase + t] * LOG2E;
            if (diag) {
                s2f[t] = make_float2(tj, pjs);
            } else {
                unsigned short* sus = reinterpret_cast<unsigned short*>(su4);
                int g = t >> 1, o = t & 1;
                sus[4 * g + o]     = __half_as_ushort(__float2half_rn(-tj));
                sus[4 * g + 2 + o] = __half_as_ushort(__float2half_rn(-pjs));
            }
        }
        const int   ig  = bi * TC + t;
        const float ti  = targ[ig];      // L1-resident (64KB dataset)
        const float pi  = pred[ig];
        const float pis = pi * LOG2E;
        __syncthreads();

        if (diag) {
            if (q == 0) {                // MSE folded in exactly once per i
                float dd = pi - ti;
                msq = fmaf(dd, dd, msq);
            }
            const int lo = q * 32;
            #pragma unroll 4
            for (int l = 0; l < 32; ++l) {
                if (lo + l > t) {
                    float2 v = s2f[l];
                    pair_body(ti, pis, v.x, v.y, sdiag, fcnt);
                }
            }
        } else {
            const unsigned hti  = h2u(__half2half2(__float2half_rn(ti)));
            const unsigned hpis = h2u(__half2half2(__float2half_rn(pis)));
            __half2 sumA = __floats2half2_rn(0.f, 0.f), sumB = sumA;
            __half2 cntA = sumA, cntB = sumA;

            #pragma unroll
            for (int s = 0; s < 8; ++s) {
                uint4 v = su4[s];
                group2(hti, hpis, v.x, v.y, C1, C2, C3, C4, C5, THR, sumA, cntA);
                group2(hti, hpis, v.z, v.w, C1, C2, C3, C4, C5, THR, sumB, cntB);
            }
            float2 fsA = __half22float2(sumA), fsB = __half22float2(sumB);
            float2 fnA = __half22float2(cntA), fnB = __half22float2(cntB);
            fsum += (fsA.x + fsA.y) + (fsB.x + fsB.y);
            fcnt += (fnA.x + fnA.y) + (fnB.x + fnB.y);
        }

        // Steal next unit; the sync also guards smem reuse.
        if (t == 0) s_next = atomicAdd(&g_unit, 1u);
        __syncthreads();
        u = s_next;
    }

    // Per-block reduction (once per block).
    float sum = 0.5f * fsum + sdiag;     // undo x2 scaling of packed path
    float fc  = fcnt;
    #pragma unroll
    for (int o = 16; o > 0; o >>= 1) {
        sum += __shfl_down_sync(0xffffffffu, sum, o);
        fc  += __shfl_down_sync(0xffffffffu, fc,  o);
        msq += __shfl_down_sync(0xffffffffu, msq, o);
    }
    const int lane = t & 31, warp = t >> 5;
    if (lane == 0) { red[0][warp] = sum; red[1][warp] = fc; red[2][warp] = msq; }
    __syncthreads();

    if (t == 0) {
        float bs = 0.f, bc = 0.f, bm = 0.f;
        #pragma unroll
        for (int w = 0; w < TC / 32; ++w) {
            bs += red[0][w]; bc += red[1][w]; bm += red[2][w];
        }
        atomicAdd(&g_sum, (double)bs);
        atomicAdd(&g_cnt, (unsigned long long)(bc + 0.5f));
        if (bm != 0.0f) atomicAdd(&g_mse, (double)bm);

        __threadfence();
        unsigned prev = atomicAdd(&g_done, 1u);
        if (prev == GRID - 1) {
            double res = g_mse / (double)NN;            // regression loss
            unsigned long long c = g_cnt;
            if (c > 0) res += 3.0 * LN2 * g_sum / (double)c;
            out[0] = (float)res;
            g_sum = 0.0; g_mse = 0.0; g_cnt = 0ull; g_done = 0u; g_unit = GRID;
            __threadfence();
        }
    }
}

extern "C" void kernel_launch(void* const* d_in, const int* in_sizes, int n_in,
                              void* d_out, int out_size) {
    const float* pred = (const float*)d_in[0];
    const float* targ = (const float*)d_in[1];
    float* out = (float*)d_out;
    (void)in_sizes; (void)n_in; (void)out_size;

    rk_persist<<<GRID, TC>>>(pred, targ, out);
}

// round 17
// speedup vs baseline: 1.2081x; 1.2081x over previous
#include <cuda_runtime.h>
#include <cuda_fp16.h>
#include <cstring>

#define NN     8192
#define TC     128
#define NCH    (NN / TC)                 // 64
#define NTILES (NCH * (NCH + 1) / 2)     // 2080 upper-tri tiles == grid (single wave @16/SM)
#define LOG2E  1.4426950408889634f
#define LN2    0.6931471805599453

// Device-global scratch (allocation-free). The finalizing block resets
// everything after each run so graph replays are deterministic.
static __device__ double             g_sum  = 0.0;
static __device__ double             g_mse  = 0.0;
static __device__ unsigned long long g_cnt  = 0ull;
static __device__ unsigned int       g_done = 0u;

__device__ __forceinline__ float fast_ex2(float x) {
    float y; asm("ex2.approx.ftz.f32 %0, %1;" : "=f"(y) : "f"(x)); return y;
}
__device__ __forceinline__ float fast_lg2(float x) {
    float y; asm("lg2.approx.ftz.f32 %0, %1;" : "=f"(y) : "f"(x)); return y;
}
__device__ __forceinline__ unsigned h2u(__half2 h) {
    unsigned u; memcpy(&u, &h, 4); return u;
}
__device__ __forceinline__ __half2 u2h(unsigned u) {
    __half2 h; memcpy(&h, &u, 4); return h;
}

// tiles before row b (rows bi <= bj): b*NCH - b(b-1)/2
__device__ __forceinline__ int tri_off(int b) { return b * NCH - (b * (b - 1)) / 2; }

// Full-precision scalar pair body (diagonal tiles only, ~3% of work).
__device__ __forceinline__ void pair_body(float ti, float pis, float tj, float pjs,
                                          float& sum, float& cnt) {
    float dt  = ti  - tj;
    float dps = pis - pjs;
    unsigned xb = __float_as_uint(dps) ^
                  ((__float_as_uint(dt) & 0x80000000u) ^ 0x80000000u);
    float u   = fast_ex2(__uint_as_float(xb));
    float l2  = fast_lg2(1.0f + u);
    float adt = fabsf(dt);
    if (adt > 0.1f) { sum = fmaf(adt, l2, sum); cnt += 1.0f; }
}

// Packed 2-pair group; EX2 fed straight from dps2 (2-link chain), sign/max
// off the critical path: z=-sign(dt)*dps; 2*log2(1+2^z)=2max(z,0)+2log2(1+2^-|dps|)
__device__ __forceinline__ void group2(unsigned hti, unsigned hpis,
                                       unsigned ntu, unsigned npu,
                                       const __half2& C1, const __half2& C2,
                                       const __half2& C3, const __half2& C4,
                                       const __half2& C5, const __half2& THR,
                                       __half2& sumh, __half2& cnth) {
    unsigned dt2  = h2u(__hadd2(u2h(hti),  u2h(ntu)));
    unsigned dps2 = h2u(__hadd2(u2h(hpis), u2h(npu)));
    unsigned nz2  = dps2 | 0x80008000u;                    // -|dps|
    unsigned uu;
    asm("ex2.approx.f16x2 %0, %1;" : "=r"(uu) : "r"(nz2)); // u = 2^-|z|
    unsigned az2  = dps2 & 0x7FFF7FFFu;                    // |z|
    unsigned sd2  = dps2 ^ (dt2 & 0x80008000u);            // sign(dt)*dps
    __half2 mm2   = __hsub2(u2h(az2), u2h(sd2));           // 2*max(z,0)
    __half2 uh    = u2h(uu);
    __half2 qp    = __hfma2(uh, C5, C4);
    qp = __hfma2(qp, uh, C3);
    qp = __hfma2(qp, uh, C2);
    qp = __hfma2(qp, uh, C1);
    __half2 l2x2  = __hfma2(qp, uh, mm2);                  // 2*log2(1+2^z)
    __half2 adt2  = u2h(dt2 & 0x7FFF7FFFu);
    __half2 ones  = __hgt2(adt2, THR);                     // 1.0 / 0.0
    __half2 wad   = __hmul2(adt2, ones);
    cnth = __hadd2(cnth, ones);
    sumh = __hfma2(wad, l2x2, sumh);
}

__global__ __launch_bounds__(TC, 16)    // force 32 regs -> 64 warps/SM (100% occ)
void rk_tile(const float* __restrict__ pred, const float* __restrict__ targ,
             float* __restrict__ out) {
    // Packed smem: slot q (uint4) = [nt2(4q,4q+1) | np2(4q,4q+1) | nt2(4q+2,4q+3) | np2(4q+2,4q+3)]
    __shared__ uint4   su4[TC / 4];
    __shared__ float2  s2f[TC];          // f32 (t, p*log2e), diagonal tiles only
    __shared__ float   red[3][TC / 32];

    const int t = threadIdx.x;

    // 2*log2(1+u) = u*(C1 + u*(C2 + u*(C3 + u*(C4 + u*C5)))), u in (0,1]
    const __half2 C1 = __floats2half2_rn(2.884924f, 2.884924f);
    const __half2 C2 = __floats2half2_rn(-1.430090f, -1.430090f);
    const __half2 C3 = __floats2half2_rn(0.870912f, 0.870912f);
    const __half2 C4 = __floats2half2_rn(-0.438334f, -0.438334f);
    const __half2 C5 = __floats2half2_rn(0.112588f, 0.112588f);
    const __half2 THR = __floats2half2_rn(0.1f, 0.1f);

    // decode tile id -> (bi, bj), bi <= bj
    const int k = (int)blockIdx.x;
    float disc = (float)((2 * NCH + 1) * (2 * NCH + 1) - 8 * k);
    int bi = (int)(((float)(2 * NCH + 1) - sqrtf(disc)) * 0.5f);
    bi = min(max(bi, 0), NCH - 1);
    while (bi + 1 <= NCH - 1 && tri_off(bi + 1) <= k) ++bi;
    while (tri_off(bi) > k) --bi;
    const int bj = bi + (k - tri_off(bi));
    const bool diag = (bi == bj);

    float fsum = 0.f;                    // off-diag, log2-domain, x2 scaled
    float sdiag = 0.f;                   // diag, log2-domain, unscaled
    float fcnt = 0.f, msq = 0.f;

    const int jg = bj * TC + t;
    const int ig = bi * TC + t;
    const float tj  = targ[jg];
    const float pjs = pred[jg] * LOG2E;
    {   // packed half stores: thread j=t fills its two ushorts
        unsigned short* sus = reinterpret_cast<unsigned short*>(su4);
        int g = t >> 1, o = t & 1;
        sus[4 * g + o]     = __half_as_ushort(__float2half_rn(-tj));
        sus[4 * g + 2 + o] = __half_as_ushort(__float2half_rn(-pjs));
    }
    const float ti  = targ[ig];
    const float pi  = pred[ig];
    const float pis = pi * LOG2E;
    if (diag) s2f[t] = make_float2(tj, pjs);
    __syncthreads();

    if (diag) {
        float dd = pi - ti;
        msq = fmaf(dd, dd, msq);
        #pragma unroll 4
        for (int j = t + 1; j < TC; ++j) {
            float2 v = s2f[j];
            pair_body(ti, pis, v.x, v.y, sdiag, fcnt);
        }
    } else {
        const unsigned hti  = h2u(__half2half2(__float2half_rn(ti)));
        const unsigned hpis = h2u(__half2half2(__float2half_rn(pis)));
        // Dual independent accumulator chains.
        __half2 sumA = __floats2half2_rn(0.f, 0.f), sumB = sumA;
        __half2 cntA = sumA, cntB = sumA;

        #pragma unroll 8
        for (int q = 0; q < TC / 4; ++q) {
            uint4 v = su4[q];
            group2(hti, hpis, v.x, v.y, C1, C2, C3, C4, C5, THR, sumA, cntA);
            group2(hti, hpis, v.z, v.w, C1, C2, C3, C4, C5, THR, sumB, cntB);
        }
        float2 fsA = __half22float2(sumA), fsB = __half22float2(sumB);
        float2 fnA = __half22float2(cntA), fnB = __half22float2(cntB);
        fsum = (fsA.x + fsA.y) + (fsB.x + fsB.y);
        fcnt = (fnA.x + fnA.y) + (fnB.x + fnB.y);
    }

    // Per-block reduction.
    float sum = 0.5f * fsum + sdiag;     // undo x2 scaling of packed path
    float fc  = fcnt;
    #pragma unroll
    for (int o = 16; o > 0; o >>= 1) {
        sum += __shfl_down_sync(0xffffffffu, sum, o);
        fc  += __shfl_down_sync(0xffffffffu, fc,  o);
        msq += __shfl_down_sync(0xffffffffu, msq, o);
    }
    const int lane = t & 31, warp = t >> 5;
    if (lane == 0) { red[0][warp] = sum; red[1][warp] = fc; red[2][warp] = msq; }
    __syncthreads();

    if (t == 0) {
        float bs = 0.f, bc = 0.f, bm = 0.f;
        #pragma unroll
        for (int w = 0; w < TC / 32; ++w) {
            bs += red[0][w]; bc += red[1][w]; bm += red[2][w];
        }
        atomicAdd(&g_sum, (double)bs);
        atomicAdd(&g_cnt, (unsigned long long)(bc + 0.5f));
        if (diag) atomicAdd(&g_mse, (double)bm);

        // Last block finalizes + resets for the next graph replay.
        __threadfence();
        unsigned prev = atomicAdd(&g_done, 1u);
        if (prev == NTILES - 1) {
            double res = g_mse / (double)NN;            // regression loss
            unsigned long long c = g_cnt;
            if (c > 0) res += 3.0 * LN2 * g_sum / (double)c;
            out[0] = (float)res;
            g_sum = 0.0; g_mse = 0.0; g_cnt = 0ull; g_done = 0u;
            __threadfence();
        }
    }
}

extern "C" void kernel_launch(void* const* d_in, const int* in_sizes, int n_in,
                              void* d_out, int out_size) {
    const float* pred = (const float*)d_in[0];
    const float* targ = (const float*)d_in[1];
    float* out = (float*)d_out;
    (void)in_sizes; (void)n_in; (void)out_size;

    rk_tile<<<NTILES, TC>>>(pred, targ, out);
}